// round 9
// baseline (speedup 1.0000x reference)
#include <cuda_runtime.h>

// Soft_NN forward == exact 1-NN: out[b,n,:] = y_c[b, argmin_m dist(x[b,n], y[b,m]), :]
// dist = fmaf(-2, s, fl(x2+y2)); s, x2, y2 all sequential-k fp32 FMA chains —
// bit-identical to the R5/R7 passing kernels (rel_err 0.0). Rounding is NOT changed.
// R8: pairs along m (zero pack-MOVs via duplicated-X smem), x2/y2 pre-kernel into
//     __device__ scratch, double-buffered Ys with 1 barrier per chunk, 256 thr.

#define B_   4
#define N_   4096
#define M_   4096
#define C_   32
#define BN   128
#define BM   128
#define NTHR 256
#define NCHUNK (M_ / BM)      // 32
#define XDSTR 264             // duplicated-X row stride (floats), 16B-aligned rows
#define YSTR  132             // Ys row stride (floats), 16B-aligned rows

typedef unsigned long long u64v;

__device__ float g_x2[B_ * N_];
__device__ float g_y2[B_ * M_];

static __device__ __forceinline__ u64v pack2(float lo, float hi) {
    u64v r;
    asm("mov.b64 %0, {%1, %2};" : "=l"(r)
        : "r"(__float_as_uint(lo)), "r"(__float_as_uint(hi)));
    return r;
}
static __device__ __forceinline__ u64v fma2(u64v a, u64v b, u64v c) {
    u64v d;
    asm("fma.rn.f32x2 %0, %1, %2, %3;" : "=l"(d) : "l"(a), "l"(b), "l"(c));
    return d;
}
static __device__ __forceinline__ u64v add2(u64v a, u64v b) {
    u64v d;
    asm("add.rn.f32x2 %0, %1, %2;" : "=l"(d) : "l"(a), "l"(b));
    return d;
}
static __device__ __forceinline__ void unpack2(u64v v, float& lo, float& hi) {
    unsigned ulo, uhi;
    asm("mov.b64 {%0, %1}, %2;" : "=r"(ulo), "=r"(uhi) : "l"(v));
    lo = __uint_as_float(ulo);
    hi = __uint_as_float(uhi);
}

// ---- pre-kernel: squared norms, sequential c-order chain (reference rounding) ----
__global__ void sq_norms_kernel(const float* __restrict__ x,
                                const float* __restrict__ y)
{
    int idx = blockIdx.x * blockDim.x + threadIdx.x;   // 0 .. 32767
    const float4* s4;
    float* dst;
    if (idx < B_ * N_) {
        s4 = (const float4*)(x + (size_t)idx * C_);
        dst = g_x2 + idx;
    } else {
        int r = idx - B_ * N_;
        s4 = (const float4*)(y + (size_t)r * C_);
        dst = g_y2 + r;
    }
    float s = 0.f;
    #pragma unroll
    for (int r = 0; r < 8; r++) {
        float4 v = s4[r];
        s = fmaf(v.x, v.x, s); s = fmaf(v.y, v.y, s);
        s = fmaf(v.z, v.z, s); s = fmaf(v.w, v.w, s);
    }
    *dst = s;
}

// smem (floats): Xd[32][XDSTR] | Ys0[32][YSTR] | Ys1[32][YSTR]
#define SMEM_FLOATS (C_ * XDSTR + 2 * C_ * YSTR)

__global__ __launch_bounds__(NTHR, 1)
void soft_nn_kernel(const float* __restrict__ x,
                    const float* __restrict__ y,
                    const float* __restrict__ yc,
                    float* __restrict__ out)
{
    extern __shared__ __align__(16) float smem[];
    float (*Xd)[XDSTR] = (float(*)[XDSTR])smem;          // duplicated X, transposed
    float* YsBase = smem + C_ * XDSTR;                   // two [C_][YSTR] buffers

    const int tid = threadIdx.x;
    const int tx  = tid & 15;        // 16 m-lanes, 8 m each (4 pairs)
    const int ty  = tid >> 4;        // 16 n-lanes, 8 n each
    const int blk = blockIdx.x;      // 0..127
    const int b   = blk >> 5;
    const int n0  = (blk & 31) * BN;

    const float4* xg  = (const float4*)(x + ((size_t)b * N_ + n0) * C_);
    const float4* yg  = (const float4*)(y + (size_t)b * M_ * C_);
    const float*  y2g = g_y2 + b * M_;

    // ---- prologue: chunk0 LDG first (latency), then X tile duplicated ----
    float4 pf[4];
    #pragma unroll
    for (int r = 0; r < 4; r++) pf[r] = yg[tid + NTHR * r];

    #pragma unroll
    for (int t = tid; t < BN * C_ / 4; t += NTHR) {
        int n  = t >> 3;             // 8 float4 per row (C=32)
        int c4 = (t & 7) << 2;
        float4 v = xg[t];
        *(float2*)&Xd[c4 + 0][2 * n] = make_float2(v.x, v.x);
        *(float2*)&Xd[c4 + 1][2 * n] = make_float2(v.y, v.y);
        *(float2*)&Xd[c4 + 2][2 * n] = make_float2(v.z, v.z);
        *(float2*)&Xd[c4 + 3][2 * n] = make_float2(v.w, v.w);
    }

    // x2 dup pairs for this thread's 8 queries (pre-kernel output)
    u64v x2d[8];
    {
        const float* x2p = g_x2 + b * N_ + n0 + ty * 8;
        #pragma unroll
        for (int i = 0; i < 8; i++) { float v = x2p[i]; x2d[i] = pack2(v, v); }
    }

    // store chunk0 into buffer 0
    #pragma unroll
    for (int r = 0; r < 4; r++) {
        int t  = tid + NTHR * r;
        int m  = t >> 3;
        int c4 = (t & 7) << 2;
        float4 v = pf[r];
        YsBase[(c4 + 0) * YSTR + m] = v.x;
        YsBase[(c4 + 1) * YSTR + m] = v.y;
        YsBase[(c4 + 2) * YSTR + m] = v.z;
        YsBase[(c4 + 3) * YSTR + m] = v.w;
    }
    __syncthreads();

    const u64v NEG2 = pack2(-2.0f, -2.0f);

    float bestd[8];
    int   bestm[8];
    #pragma unroll
    for (int i = 0; i < 8; i++) { bestd[i] = 3.4e38f; bestm[i] = 0; }

    for (int ic = 0; ic < NCHUNK; ic++) {
        const int mc = ic * BM;
        const float* Yc = YsBase + (ic & 1) * (C_ * YSTR);

        // prefetch next chunk (consumed after compute; latency fully hidden)
        if (ic + 1 < NCHUNK) {
            const float4* ygn = yg + ((mc + BM) * C_) / 4;
            #pragma unroll
            for (int r = 0; r < 4; r++) pf[r] = ygn[tid + NTHR * r];
        }

        // y2 pairs for this thread's 8 candidates (L2-resident LDG)
        ulonglong2 ylo = *(const ulonglong2*)(y2g + mc + tx * 4);
        ulonglong2 yhi = *(const ulonglong2*)(y2g + mc + 64 + tx * 4);
        u64v y2pr[4] = { ylo.x, ylo.y, yhi.x, yhi.y };

        // ---- mainloop: 6 LDS.128 + 32 FFMA2 per k, no MOVs ----
        u64v acc[8][4];
        #pragma unroll
        for (int i = 0; i < 8; i++)
            #pragma unroll
            for (int j2 = 0; j2 < 4; j2++) acc[i][j2] = 0ULL;

        #pragma unroll 8
        for (int k = 0; k < C_; k++) {
            ulonglong2 xa = *(const ulonglong2*)&Xd[k][ty * 16];      // (x0,x0),(x1,x1)
            ulonglong2 xb = *(const ulonglong2*)&Xd[k][ty * 16 + 4];
            ulonglong2 xc = *(const ulonglong2*)&Xd[k][ty * 16 + 8];
            ulonglong2 xe = *(const ulonglong2*)&Xd[k][ty * 16 + 12];
            const float* yrow = Yc + k * YSTR;
            ulonglong2 pa = *(const ulonglong2*)&yrow[tx * 4];        // (m0,m1),(m2,m3)
            ulonglong2 pb = *(const ulonglong2*)&yrow[64 + tx * 4];
            u64v xdv[8] = { xa.x, xa.y, xb.x, xb.y, xc.x, xc.y, xe.x, xe.y };
            u64v ypv[4] = { pa.x, pa.y, pb.x, pb.y };
            #pragma unroll
            for (int i = 0; i < 8; i++)
                #pragma unroll
                for (int j2 = 0; j2 < 4; j2++)
                    acc[i][j2] = fma2(xdv[i], ypv[j2], acc[i][j2]);
        }

        // ---- packed epilogue: d = fma2(acc, -2, add2(x2,y2)) (identical rounding) ----
        #pragma unroll
        for (int j2 = 0; j2 < 4; j2++) {
            int mlo = mc + ((j2 < 2) ? (tx * 4 + j2 * 2)
                                     : (64 + tx * 4 + (j2 - 2) * 2));
            #pragma unroll
            for (int i = 0; i < 8; i++) {
                u64v d2 = fma2(acc[i][j2], NEG2, add2(x2d[i], y2pr[j2]));
                float dlo, dhi;
                unpack2(d2, dlo, dhi);
                // lo before hi, j2 ascending, chunks ascending: strict < keeps earliest m
                if (dlo < bestd[i]) { bestd[i] = dlo; bestm[i] = mlo; }
                if (dhi < bestd[i]) { bestd[i] = dhi; bestm[i] = mlo + 1; }
            }
        }

        // ---- store next chunk into the other buffer (safe: read last in ic-1) ----
        if (ic + 1 < NCHUNK) {
            float* Yn = YsBase + ((ic + 1) & 1) * (C_ * YSTR);
            #pragma unroll
            for (int r = 0; r < 4; r++) {
                int t  = tid + NTHR * r;
                int m  = t >> 3;
                int c4 = (t & 7) << 2;
                float4 v = pf[r];
                Yn[(c4 + 0) * YSTR + m] = v.x;
                Yn[(c4 + 1) * YSTR + m] = v.y;
                Yn[(c4 + 2) * YSTR + m] = v.z;
                Yn[(c4 + 3) * YSTR + m] = v.w;
            }
        }
        __syncthreads();   // single barrier per chunk
    }

    // ---- cross-tx reduction (reuse smem as scratch) ----
    float* redD = smem;               // 2048 floats
    int*   redM = (int*)(smem + BN * 16);
    #pragma unroll
    for (int i = 0; i < 8; i++) {
        int n = ty * 8 + i;
        redD[n * 16 + tx] = bestd[i];
        redM[n * 16 + tx] = bestm[i];
    }
    __syncthreads();
    if (tid < BN) {
        float bd = redD[tid * 16];
        int   bm = redM[tid * 16];
        #pragma unroll
        for (int t = 1; t < 16; t++) {
            float d = redD[tid * 16 + t];
            int   m = redM[tid * 16 + t];
            if (d < bd || (d == bd && m < bm)) { bd = d; bm = m; }
        }
        const float* src = yc + ((size_t)b * M_ + bm) * 3;
        float*       dst = out + ((size_t)b * N_ + n0 + tid) * 3;
        dst[0] = src[0];
        dst[1] = src[1];
        dst[2] = src[2];
    }
}

extern "C" void kernel_launch(void* const* d_in, const int* in_sizes, int n_in,
                              void* d_out, int out_size)
{
    const float* x  = (const float*)d_in[0];   // x_f  [4,4096,32]
    const float* y  = (const float*)d_in[1];   // y_f  [4,4096,32]
    const float* yc = (const float*)d_in[2];   // y_c  [4,4096,3]
    // d_in[3] = temp_inv (positive constant; does not affect argmax)
    float* out = (float*)d_out;                // [4,4096,3]

    sq_norms_kernel<<<(B_ * (N_ + M_)) / 256, 256>>>(x, y);

    const int smem_bytes = SMEM_FLOATS * (int)sizeof(float);  // ~66KB
    cudaFuncSetAttribute(soft_nn_kernel,
                         cudaFuncAttributeMaxDynamicSharedMemorySize, smem_bytes);
    soft_nn_kernel<<<(B_ * N_) / BN, NTHR, smem_bytes>>>(x, y, yc, out);
}